// round 11
// baseline (speedup 1.0000x reference)
#include <cuda_runtime.h>
#include <cuda_bf16.h>
#include <cuda_fp16.h>
#include <cstdint>
#include <math.h>

// ---------------- problem constants ----------------
#define Nn   50000
#define Ee   800000
#define FEAT 64
#define HID  128
#define EPSV 1e-5f
#define GB1 ((Nn + 127) / 128)    // 391 GEMM blocks (M-tile 128)

// ---------------- static device scratch (no allocs allowed) ----------------
__device__ float  g_T    [Nn * HID];       // fp32 scratch (enc/o1 outputs, H)
__device__ float  g_H    [Nn * HID];
__device__ float  g_Y0   [Nn * HID];
__device__ float  g_PREVF[Nn * HID];       // fp32 residual carry
__device__ __half g_YH   [Nn * HID];       // fp16 gather matrix for SpMM
__device__ uint2  g_T2   [Nn * 64];        // dual-bf16 (hi,lo) planes, k-pair major
__device__ uint2  g_P2   [Nn * 64];

__device__ int   g_deg   [Nn];
__device__ int   g_rowcnt[Nn];
__device__ int   g_rowptr[Nn + 1];
__device__ int   g_cursor[Nn];
__device__ float g_dinv  [Nn];
__device__ int   g_ccol  [Ee];
__device__ float g_cw    [Ee];

__device__ float g_part [GB1 * 256];
__device__ float g_alpha[HID];
__device__ float g_beta [HID];
__device__ int   g_is64;

// pre-converted weights: 9 slots x {hi,lo} x 8192 words, k-pair packed [k2][n]
__device__ unsigned g_Wpre[9 * 2 * 8192];

// ---------------- helpers ----------------
__device__ __forceinline__ void split2(float x, float y, unsigned& hi, unsigned& lo) {
    __nv_bfloat162 h = __floats2bfloat162_rn(x, y);   // .x = k, .y = k+1
    float rx = x - __bfloat162float(h.x);
    float ry = y - __bfloat162float(h.y);
    __nv_bfloat162 l = __floats2bfloat162_rn(rx, ry);
    hi = *(unsigned*)&h;
    lo = *(unsigned*)&l;
}

#define MMA_BF16(C, A, B0, B1)                                                \
    asm volatile(                                                             \
        "mma.sync.aligned.m16n8k16.row.col.f32.bf16.bf16.f32 "                \
        "{%0,%1,%2,%3}, {%4,%5,%6,%7}, {%8,%9}, {%0,%1,%2,%3};"               \
        : "+f"((C)[0]), "+f"((C)[1]), "+f"((C)[2]), "+f"((C)[3])              \
        : "r"((A)[0]), "r"((A)[1]), "r"((A)[2]), "r"((A)[3]),                 \
          "r"(B0), "r"(B1))

// ---------------- weight pre-conversion: W[K,128] -> packed bf16 hi/lo -----
__global__ void k_prepw(const float* __restrict__ W_in, const float* __restrict__ Wf,
                        const float* __restrict__ Wa, const float* __restrict__ W_o1,
                        const float* __restrict__ W_o2) {
    int s = blockIdx.x;
    const float* W; int K;
    if (s == 0)      { W = W_in;                 K = 64;  }
    else if (s < 4)  { W = Wf + (s - 1) * 16384; K = 128; }
    else if (s < 7)  { W = Wa + (s - 4) * 16384; K = 128; }
    else if (s == 7) { W = W_o1;                 K = 128; }
    else             { W = W_o2;                 K = 128; }
    int total = 128 * (K / 2);
    for (int idx = threadIdx.x; idx < total; idx += 256) {
        int n = idx & 127, k = (idx >> 7) * 2;
        float v0 = W[k * 128 + n];
        float v1 = W[(k + 1) * 128 + n];
        unsigned hi, lo; split2(v0, v1, hi, lo);
        g_Wpre[(s * 2 + 0) * 8192 + idx] = hi;
        g_Wpre[(s * 2 + 1) * 8192 + idx] = lo;
    }
}

// ---------------- split-bf16 tensor-core GEMM, M-tile 128 ------------------
// C[M,128] = A[M,K] @ W[K,128]; 3-term split (hi*hi + hi*lo + lo*hi).
// AFMT 0: A fp32, in-loop split.  AFMT 1: A2 dual-bf16 (hi,lo) uint2 planes.
// EPI: 0 = +bias, 1 = sigmoid, 2 = *Mul, 3 = *Mul^2
// WH: write fp16 g_YH; WD: write dual D2; WF: write fp32 C; STATS: partials.
template <int K, int EPI, int AFMT, int WH, int WD, int WF, int STATS>
__global__ void __launch_bounds__(256, 2)
k_gemm(const float* __restrict__ A, const uint2* __restrict__ A2,
       const unsigned* __restrict__ BH, const unsigned* __restrict__ BL,
       const float* __restrict__ bias, const float* __restrict__ Mm,
       float* __restrict__ C, uint2* __restrict__ D2) {
    constexpr int KP = K / 2;                 // k-pair rows of B
    constexpr int NT = K / 16;                // k tiles
    extern __shared__ unsigned smem_u[];
    unsigned (*Bs_hi)[136] = reinterpret_cast<unsigned(*)[136]>(smem_u);
    unsigned (*Bs_lo)[136] = reinterpret_cast<unsigned(*)[136]>(smem_u + KP * 136);

    const int tid    = threadIdx.x;
    const int lane   = tid & 31;
    const int warp   = tid >> 5;
    const int bm     = blockIdx.x * 128;
    const int warp_m = (warp >> 1) * 32;
    const int warp_n = (warp & 1) * 64;
    const int grp    = lane >> 2;
    const int tig    = lane & 3;

    // ---- stage B: pure uint4 copy of pre-split, pre-packed weights -------
    for (int idx = tid; idx < KP * 32; idx += 256) {
        int r = idx >> 5, c = (idx & 31) << 2;
        *(uint4*)&Bs_hi[r][c] = *(const uint4*)(BH + r * 128 + c);
        *(uint4*)&Bs_lo[r][c] = *(const uint4*)(BL + r * 128 + c);
    }

    // A fragment row pointers: rows r = 2t + h -> warp_m + 16t + 8h + grp
    const float* arow[4];
    const uint2* arow2[4];
    bool avld[4];
#pragma unroll
    for (int r = 0; r < 4; r++) {
        int row = bm + warp_m + 16 * (r >> 1) + 8 * (r & 1) + grp;
        avld[r] = row < Nn;
        int rr = avld[r] ? row : 0;
        if (AFMT == 0) arow[r]  = A  + (size_t)rr * K + 2 * tig;
        else           arow2[r] = A2 + (size_t)rr * KP + tig;
    }

    float acc[2][8][4];
#pragma unroll
    for (int t = 0; t < 2; t++)
#pragma unroll
        for (int j = 0; j < 8; j++)
#pragma unroll
            for (int i = 0; i < 4; i++) acc[t][j][i] = 0.f;

    // prefetch ktile 0
    float2 pv[4][2];
    uint2  pv2[4][2];
#pragma unroll
    for (int r = 0; r < 4; r++)
#pragma unroll
        for (int p = 0; p < 2; p++) {
            if (AFMT == 0)
                pv[r][p]  = avld[r] ? *(const float2*)(arow[r] + 8 * p)
                                    : make_float2(0.f, 0.f);
            else
                pv2[r][p] = avld[r] ? arow2[r][4 * p] : make_uint2(0u, 0u);
        }

    __syncthreads();   // B ready; no further barriers until epilogue

#pragma unroll
    for (int kt = 0; kt < NT; kt++) {
        unsigned ahi[2][4], alo[2][4];
#pragma unroll
        for (int t = 0; t < 2; t++)
#pragma unroll
            for (int h = 0; h < 2; h++)
#pragma unroll
                for (int p = 0; p < 2; p++) {
                    if (AFMT == 0) {
                        split2(pv[2 * t + h][p].x, pv[2 * t + h][p].y,
                               ahi[t][h + 2 * p], alo[t][h + 2 * p]);
                    } else {
                        ahi[t][h + 2 * p] = pv2[2 * t + h][p].x;
                        alo[t][h + 2 * p] = pv2[2 * t + h][p].y;
                    }
                }
        if (kt + 1 < NT) {
#pragma unroll
            for (int r = 0; r < 4; r++)
#pragma unroll
                for (int p = 0; p < 2; p++) {
                    if (AFMT == 0)
                        pv[r][p] = avld[r]
                            ? *(const float2*)(arow[r] + 16 * (kt + 1) + 8 * p)
                            : make_float2(0.f, 0.f);
                    else
                        pv2[r][p] = avld[r]
                            ? arow2[r][8 * (kt + 1) + 4 * p]
                            : make_uint2(0u, 0u);
                }
        }

        const int koff = kt * 8;
#pragma unroll
        for (int j = 0; j < 8; j++) {
            int n = warp_n + 8 * j + grp;
            unsigned bh0 = Bs_hi[koff + tig][n];
            unsigned bh1 = Bs_hi[koff + tig + 4][n];
            unsigned bl0 = Bs_lo[koff + tig][n];
            unsigned bl1 = Bs_lo[koff + tig + 4][n];
#pragma unroll
            for (int t = 0; t < 2; t++) {
                MMA_BF16(acc[t][j], ahi[t], bh0, bh1);
                MMA_BF16(acc[t][j], ahi[t], bl0, bl1);
                MMA_BF16(acc[t][j], alo[t], bh0, bh1);
            }
        }
    }

    // ---- epilogue (+ optional fused BN stats partials) -------------------
    float* sred = (float*)smem_u;
    if (STATS) __syncthreads();

#pragma unroll
    for (int j = 0; j < 8; j++) {
        int col = warp_n + 8 * j + 2 * tig;
        float s0 = 0.f, s1 = 0.f, q0 = 0.f, q1 = 0.f;
#pragma unroll
        for (int t = 0; t < 2; t++) {
#pragma unroll
            for (int h = 0; h < 2; h++) {
                int row = bm + warp_m + 16 * t + grp + h * 8;
                if (row >= Nn) continue;
                float v0 = acc[t][j][h * 2 + 0];
                float v1 = acc[t][j][h * 2 + 1];
                if (EPI == 0) {
                    v0 += bias[col]; v1 += bias[col + 1];
                } else if (EPI == 1) {
                    v0 = 1.f / (1.f + __expf(-v0));
                    v1 = 1.f / (1.f + __expf(-v1));
                } else if (EPI == 2) {
                    float2 m = *(const float2*)(Mm + (size_t)row * 128 + col);
                    v0 *= m.x; v1 *= m.y;
                } else if (EPI == 3) {
                    float2 m = *(const float2*)(Mm + (size_t)row * 128 + col);
                    v0 *= m.x * m.x; v1 *= m.y * m.y;
                }
                if (WF) {
                    float2 o; o.x = v0; o.y = v1;
                    *(float2*)(C + (size_t)row * 128 + col) = o;
                }
                if (WH) {
                    *(__half2*)(g_YH + (size_t)row * 128 + col) =
                        __floats2half2_rn(v0, v1);
                }
                if (WD) {
                    unsigned hi, lo; split2(v0, v1, hi, lo);
                    D2[(size_t)row * 64 + (col >> 1)] = make_uint2(hi, lo);
                }
                if (STATS) {
                    s0 += v0; q0 = fmaf(v0, v0, q0);
                    s1 += v1; q1 = fmaf(v1, v1, q1);
                }
            }
        }
        if (STATS) {
#pragma unroll
            for (int msk = 4; msk <= 16; msk <<= 1) {
                s0 += __shfl_xor_sync(0xffffffffu, s0, msk);
                s1 += __shfl_xor_sync(0xffffffffu, s1, msk);
                q0 += __shfl_xor_sync(0xffffffffu, q0, msk);
                q1 += __shfl_xor_sync(0xffffffffu, q1, msk);
            }
            if (grp == 0) {
                int base = ((warp * 8 + j) * 4 + tig) * 2;
                sred[base + 0]       = s0;
                sred[base + 1]       = s1;
                sred[512 + base + 0] = q0;
                sred[512 + base + 1] = q1;
            }
        }
    }
    if (STATS) {
        __syncthreads();
        if (tid < 128) {
            int p  = tid >> 6;
            int rm = tid & 63;
            int j  = rm >> 3;
            int tg = (rm & 7) >> 1;
            int b  = tid & 1;
            float s = 0.f, q = 0.f;
#pragma unroll
            for (int i = 0; i < 4; i++) {
                int w = p + 2 * i;
                int base = ((w * 8 + j) * 4 + tg) * 2 + b;
                s += sred[base];
                q += sred[512 + base];
            }
            g_part[blockIdx.x * 256 + tid]       = s;
            g_part[blockIdx.x * 256 + 128 + tid] = q;
        }
    }
}

// ---------------- graph preprocessing ----------------
__global__ void k_zero_counts() {
    int i = blockIdx.x * blockDim.x + threadIdx.x;
    if (i < Nn) { g_deg[i] = 0; g_rowcnt[i] = 0; }
}

__global__ void k_detect(const int* __restrict__ ei) {
    if (threadIdx.x == 0 && blockIdx.x == 0) {
        int all0 = 1;
        for (int i = 0; i < 32; i++) {
            if (ei[2 * i + 1] != 0) { all0 = 0; break; }
        }
        g_is64 = all0;
    }
}

__global__ void k_hist(const void* __restrict__ eiv) {
    int e = blockIdx.x * blockDim.x + threadIdx.x;
    if (e >= Ee) return;
    int r, c;
    if (g_is64) {
        const long long* p = (const long long*)eiv;
        r = (int)p[e]; c = (int)p[Ee + e];
    } else {
        const int* p = (const int*)eiv;
        r = p[e]; c = p[Ee + e];
    }
    if (r != c) {
        atomicAdd(&g_deg[c], 1);
        atomicAdd(&g_rowcnt[r], 1);
    }
}

__global__ void k_dinv() {
    int i = blockIdx.x * blockDim.x + threadIdx.x;
    if (i < Nn) g_dinv[i] = rsqrtf((float)(g_deg[i] + 1));
}

__global__ void k_scan() {
    __shared__ int s[1024];
    const int t  = threadIdx.x;
    const int CH = (Nn + 1023) / 1024;
    int base = t * CH;
    int sum = 0;
    for (int i = 0; i < CH; i++) {
        int idx = base + i;
        if (idx < Nn) sum += g_rowcnt[idx];
    }
    s[t] = sum;
    __syncthreads();
    for (int off = 1; off < 1024; off <<= 1) {
        int v = (t >= off) ? s[t - off] : 0;
        __syncthreads();
        s[t] += v;
        __syncthreads();
    }
    int run = s[t] - sum;
    for (int i = 0; i < CH; i++) {
        int idx = base + i;
        if (idx < Nn) {
            g_rowptr[idx] = run;
            g_cursor[idx] = run;
            run += g_rowcnt[idx];
        }
    }
    if (t == 1023) g_rowptr[Nn] = s[1023];
}

__global__ void k_fill(const void* __restrict__ eiv) {
    int e = blockIdx.x * blockDim.x + threadIdx.x;
    if (e >= Ee) return;
    int r, c;
    if (g_is64) {
        const long long* p = (const long long*)eiv;
        r = (int)p[e]; c = (int)p[Ee + e];
    } else {
        const int* p = (const int*)eiv;
        r = p[e]; c = p[Ee + e];
    }
    if (r != c) {
        int pos = atomicAdd(&g_cursor[r], 1);
        g_ccol[pos] = c;
        g_cw[pos]   = g_dinv[r] * g_dinv[c];
    }
}

// ---------------- SpMM: fp16 gather (g_YH) -> dual-bf16 output -------------
__global__ void __launch_bounds__(256) k_spmm(uint2* __restrict__ out) {
    int w    = (blockIdx.x * 256 + threadIdx.x) >> 5;
    int lane = threadIdx.x & 31;
    if (w >= Nn) return;
    int s = g_rowptr[w], e = g_rowptr[w + 1];
    const uint2* yh = (const uint2*)g_YH;   // 4 halfs per uint2; row stride 32
    float4 acc = make_float4(0.f, 0.f, 0.f, 0.f);
    int i = s;
    for (; i + 3 < e; i += 4) {
        int   c0 = __ldg(&g_ccol[i]);
        int   c1 = __ldg(&g_ccol[i + 1]);
        int   c2 = __ldg(&g_ccol[i + 2]);
        int   c3 = __ldg(&g_ccol[i + 3]);
        float w0 = __ldg(&g_cw[i]);
        float w1 = __ldg(&g_cw[i + 1]);
        float w2 = __ldg(&g_cw[i + 2]);
        float w3 = __ldg(&g_cw[i + 3]);
        uint2 r0 = __ldg(&yh[(size_t)c0 * 32 + lane]);
        uint2 r1 = __ldg(&yh[(size_t)c1 * 32 + lane]);
        uint2 r2 = __ldg(&yh[(size_t)c2 * 32 + lane]);
        uint2 r3 = __ldg(&yh[(size_t)c3 * 32 + lane]);
        float2 a0 = __half22float2(*(__half2*)&r0.x), b0 = __half22float2(*(__half2*)&r0.y);
        float2 a1 = __half22float2(*(__half2*)&r1.x), b1 = __half22float2(*(__half2*)&r1.y);
        float2 a2 = __half22float2(*(__half2*)&r2.x), b2 = __half22float2(*(__half2*)&r2.y);
        float2 a3 = __half22float2(*(__half2*)&r3.x), b3 = __half22float2(*(__half2*)&r3.y);
        acc.x = fmaf(w0, a0.x, acc.x); acc.y = fmaf(w0, a0.y, acc.y);
        acc.z = fmaf(w0, b0.x, acc.z); acc.w = fmaf(w0, b0.y, acc.w);
        acc.x = fmaf(w1, a1.x, acc.x); acc.y = fmaf(w1, a1.y, acc.y);
        acc.z = fmaf(w1, b1.x, acc.z); acc.w = fmaf(w1, b1.y, acc.w);
        acc.x = fmaf(w2, a2.x, acc.x); acc.y = fmaf(w2, a2.y, acc.y);
        acc.z = fmaf(w2, b2.x, acc.z); acc.w = fmaf(w2, b2.y, acc.w);
        acc.x = fmaf(w3, a3.x, acc.x); acc.y = fmaf(w3, a3.y, acc.y);
        acc.z = fmaf(w3, b3.x, acc.z); acc.w = fmaf(w3, b3.y, acc.w);
    }
    for (; i < e; i++) {
        int   c0 = __ldg(&g_ccol[i]);
        float w0 = __ldg(&g_cw[i]);
        uint2 r0 = __ldg(&yh[(size_t)c0 * 32 + lane]);
        float2 a0 = __half22float2(*(__half2*)&r0.x), b0 = __half22float2(*(__half2*)&r0.y);
        acc.x = fmaf(w0, a0.x, acc.x); acc.y = fmaf(w0, a0.y, acc.y);
        acc.z = fmaf(w0, b0.x, acc.z); acc.w = fmaf(w0, b0.y, acc.w);
    }
    // self loop: weight = dinv^2
    float sw = g_dinv[w]; sw *= sw;
    uint2 rs = yh[(size_t)w * 32 + lane];
    float2 as = __half22float2(*(__half2*)&rs.x), bs = __half22float2(*(__half2*)&rs.y);
    acc.x = fmaf(sw, as.x, acc.x); acc.y = fmaf(sw, as.y, acc.y);
    acc.z = fmaf(sw, bs.x, acc.z); acc.w = fmaf(sw, bs.y, acc.w);
    // dual-bf16 output: k-pairs (2*lane, 2*lane+1)
    unsigned h0, l0, h1, l1;
    split2(acc.x, acc.y, h0, l0);
    split2(acc.z, acc.w, h1, l1);
    uint4 o; o.x = h0; o.y = l0; o.z = h1; o.w = l1;
    ((uint4*)out)[(size_t)w * 32 + lane] = o;
}

// ---------------- BN param computation from partials ----------------------
__global__ void k_stats2(const float* __restrict__ g, const float* __restrict__ bt,
                         int nb) {
    int c = threadIdx.x;
    float s = 0.f, q = 0.f;
    for (int b = 0; b < nb; b++) {
        s += g_part[b * 256 + c];
        q += g_part[b * 256 + 128 + c];
    }
    float mean = s / (float)Nn;
    float var  = q / (float)Nn - mean * mean;
    float a = g[c] * rsqrtf(var + EPSV);
    g_alpha[c] = a;
    g_beta[c]  = bt[c] - mean * a;
}

// ---------------- BN apply (+ReLU, optional residual, dual output) --------
template <int ADD, int WF, int WD>
__global__ void k_bn(const float* __restrict__ src, const float* __restrict__ prevIn,
                     float* __restrict__ dstF, uint2* __restrict__ dstD) {
    int i = blockIdx.x * blockDim.x + threadIdx.x;
    if (i >= Nn * 32) return;
    int c = (i & 31) * 4;
    float4 v = ((const float4*)src)[i];
    v.x = fmaxf(fmaf(g_alpha[c + 0], v.x, g_beta[c + 0]), 0.f);
    v.y = fmaxf(fmaf(g_alpha[c + 1], v.y, g_beta[c + 1]), 0.f);
    v.z = fmaxf(fmaf(g_alpha[c + 2], v.z, g_beta[c + 2]), 0.f);
    v.w = fmaxf(fmaf(g_alpha[c + 3], v.w, g_beta[c + 3]), 0.f);
    if (ADD) {
        float4 p = ((const float4*)prevIn)[i];
        v.x += p.x; v.y += p.y; v.z += p.z; v.w += p.w;
    }
    if (WF) ((float4*)dstF)[i] = v;
    if (WD) {
        unsigned h0, l0, h1, l1;
        split2(v.x, v.y, h0, l0);
        split2(v.z, v.w, h1, l1);
        uint4 o; o.x = h0; o.y = l0; o.z = h1; o.w = l1;
        ((uint4*)dstD)[i] = o;
    }
}

// ---------------- launch ----------------
static int smb(int K) { return 2 * (K / 2) * 136 * 4; }

extern "C" void kernel_launch(void* const* d_in, const int* in_sizes, int n_in,
                              void* d_out, int out_size) {
    const float* x     = (const float*)d_in[0];
    const void*  ei    = d_in[1];
    const float* W_in  = (const float*)d_in[2];
    const float* b_in  = (const float*)d_in[3];
    const float* gin   = (const float*)d_in[4];
    const float* btin  = (const float*)d_in[5];
    const float* Wf    = (const float*)d_in[6];
    const float* Wa    = (const float*)d_in[7];
    const float* gnorm = (const float*)d_in[8];
    const float* btnorm= (const float*)d_in[9];
    const float* W_o1  = (const float*)d_in[10];
    const float* b_o1  = (const float*)d_in[11];
    const float* g_o   = (const float*)d_in[12];
    const float* bt_o  = (const float*)d_in[13];
    const float* W_o2  = (const float*)d_in[14];
    const float* b_o2  = (const float*)d_in[15];
    float* out = (float*)d_out;

    float *T, *H, *Y0, *PREVF;
    uint2 *T2, *P2;
    unsigned* wpre;
    cudaGetSymbolAddress((void**)&T,     g_T);
    cudaGetSymbolAddress((void**)&H,     g_H);
    cudaGetSymbolAddress((void**)&Y0,    g_Y0);
    cudaGetSymbolAddress((void**)&PREVF, g_PREVF);
    cudaGetSymbolAddress((void**)&T2,    g_T2);
    cudaGetSymbolAddress((void**)&P2,    g_P2);
    cudaGetSymbolAddress((void**)&wpre,  g_Wpre);
    auto wh = [&](int s) { return wpre + (size_t)(s * 2 + 0) * 8192; };
    auto wl = [&](int s) { return wpre + (size_t)(s * 2 + 1) * 8192; };

    // instantiations: <K, EPI, AFMT, WH, WD, WF, STATS>
    cudaFuncSetAttribute(k_gemm<64, 0, 0, 0, 0, 1, 1>,  cudaFuncAttributeMaxDynamicSharedMemorySize, smb(64));
    cudaFuncSetAttribute(k_gemm<128, 1, 1, 1, 0, 1, 0>, cudaFuncAttributeMaxDynamicSharedMemorySize, smb(128));
    cudaFuncSetAttribute(k_gemm<128, 3, 1, 1, 0, 0, 0>, cudaFuncAttributeMaxDynamicSharedMemorySize, smb(128));
    cudaFuncSetAttribute(k_gemm<128, 2, 1, 0, 0, 1, 1>, cudaFuncAttributeMaxDynamicSharedMemorySize, smb(128));
    cudaFuncSetAttribute(k_gemm<128, 2, 1, 0, 1, 0, 0>, cudaFuncAttributeMaxDynamicSharedMemorySize, smb(128));
    cudaFuncSetAttribute(k_gemm<128, 0, 1, 0, 0, 1, 1>, cudaFuncAttributeMaxDynamicSharedMemorySize, smb(128));
    cudaFuncSetAttribute(k_gemm<128, 0, 1, 0, 0, 1, 0>, cudaFuncAttributeMaxDynamicSharedMemorySize, smb(128));

    const int NB  = (Nn + 255) / 256;
    const int EB  = (Ee + 255) / 256;
    const int EWB = (Nn * 32 + 255) / 256;

    k_zero_counts<<<NB, 256>>>();                                        // 0
    k_prepw<<<9, 256>>>(W_in, Wf, Wa, W_o1, W_o2);                       // 1
    k_detect<<<1, 32>>>((const int*)ei);                                 // 2
    k_gemm<64, 0, 0, 0, 0, 1, 1><<<GB1, 256, smb(64)>>>(
        x, nullptr, wh(0), wl(0), b_in, nullptr, T, nullptr);            // 3 <- profiled
    k_hist<<<EB, 256>>>(ei);                                             // 4
    k_dinv<<<NB, 256>>>();                                               // 5
    k_scan<<<1, 1024>>>();                                               // 6
    k_fill<<<EB, 256>>>(ei);                                             // 7
    k_stats2<<<1, 128>>>(gin, btin, GB1);                                // 8
    k_bn<0, 1, 1><<<EWB, 256>>>(T, nullptr, PREVF, P2);                  // 9

    for (int l = 0; l < 3; l++) {
        // y0 = sigmoid(PREV @ Wf): fp32 Y0 + fp16 g_YH
        k_gemm<128, 1, 1, 1, 0, 1, 0><<<GB1, 256, smb(128)>>>(
            nullptr, P2, wh(1 + l), wl(1 + l), nullptr, nullptr, Y0, nullptr);
        k_spmm<<<EWB, 256>>>(T2);     // T2 = A_hat @ y0 (dual out)
        // y = y0^2 * (T2 @ Wa): fp16 only
        k_gemm<128, 3, 1, 1, 0, 0, 0><<<GB1, 256, smb(128)>>>(
            nullptr, T2, wh(4 + l), wl(4 + l), nullptr, Y0, nullptr, nullptr);
        k_spmm<<<EWB, 256>>>(T2);     // T2 = A_hat @ y
        if (l < 2) {
            // h = y0 * (T2 @ Wa): fp32 H + fused stats
            k_gemm<128, 2, 1, 0, 0, 1, 1><<<GB1, 256, smb(128)>>>(
                nullptr, T2, wh(4 + l), wl(4 + l), nullptr, Y0, H, nullptr);
            k_stats2<<<1, 128>>>(gnorm + l * 128, btnorm + l * 128, GB1);
            k_bn<1, 1, 1><<<EWB, 256>>>(H, PREVF, PREVF, P2);
        } else {
            // final layer: dual only (feeds output encoder)
            k_gemm<128, 2, 1, 0, 1, 0, 0><<<GB1, 256, smb(128)>>>(
                nullptr, T2, wh(4 + l), wl(4 + l), nullptr, Y0, nullptr, P2);
        }
    }

    // output encoder: Linear -> BN -> ReLU -> Linear
    k_gemm<128, 0, 1, 0, 0, 1, 1><<<GB1, 256, smb(128)>>>(
        nullptr, P2, wh(7), wl(7), b_o1, nullptr, T, nullptr);
    k_stats2<<<1, 128>>>(g_o, bt_o, GB1);
    k_bn<0, 0, 1><<<EWB, 256>>>(T, nullptr, nullptr, P2);
    k_gemm<128, 0, 1, 0, 0, 1, 0><<<GB1, 256, smb(128)>>>(
        nullptr, P2, wh(8), wl(8), b_o2, nullptr, out, nullptr);
}

// round 13
// speedup vs baseline: 1.0195x; 1.0195x over previous
#include <cuda_runtime.h>
#include <cuda_bf16.h>
#include <cuda_fp16.h>
#include <cstdint>
#include <math.h>

// ---------------- problem constants ----------------
#define Nn   50000
#define Ee   800000
#define FEAT 64
#define HID  128
#define EPSV 1e-5f
#define GB1 ((Nn + 127) / 128)    // 391 GEMM blocks (M-tile 128)

// ---------------- static device scratch (no allocs allowed) ----------------
__device__ float  g_T   [Nn * HID];
__device__ float  g_H   [Nn * HID];
__device__ float  g_Y0  [Nn * HID];
__device__ float  g_PREV[Nn * HID];
__device__ __half g_YH  [Nn * HID];   // fp16 gather matrix for SpMM

__device__ int   g_deg   [Nn];
__device__ int   g_rowcnt[Nn];
__device__ int   g_rowptr[Nn + 1];
__device__ int   g_cursor[Nn];
__device__ float g_dinv  [Nn];
__device__ int   g_ccol  [Ee];
__device__ float g_cw    [Ee];

__device__ float g_part [GB1 * 256];
__device__ float g_alpha[HID];
__device__ float g_beta [HID];
__device__ int   g_is64;

// pre-converted weights: 9 slots x {hi,lo} x 8192 words.
// paired layout: uint2 pair[(kt*4+tig)][n] = {plane(k2=kt*8+tig,n), plane(k2=kt*8+tig+4,n)}
__device__ unsigned g_Wpre[9 * 2 * 8192];

// ---------------- helpers ----------------
__device__ __forceinline__ void split2(float x, float y, unsigned& hi, unsigned& lo) {
    __nv_bfloat162 h = __floats2bfloat162_rn(x, y);   // .x = k, .y = k+1
    float rx = x - __bfloat162float(h.x);
    float ry = y - __bfloat162float(h.y);
    __nv_bfloat162 l = __floats2bfloat162_rn(rx, ry);
    hi = *(unsigned*)&h;
    lo = *(unsigned*)&l;
}

#define MMA_BF16(C, A, B0, B1)                                                \
    asm volatile(                                                             \
        "mma.sync.aligned.m16n8k16.row.col.f32.bf16.bf16.f32 "                \
        "{%0,%1,%2,%3}, {%4,%5,%6,%7}, {%8,%9}, {%0,%1,%2,%3};"               \
        : "+f"((C)[0]), "+f"((C)[1]), "+f"((C)[2]), "+f"((C)[3])              \
        : "r"((A)[0]), "r"((A)[1]), "r"((A)[2]), "r"((A)[3]),                 \
          "r"(B0), "r"(B1))

// ---------------- weight pre-conversion -> paired bf16 hi/lo ---------------
__global__ void k_prepw(const float* __restrict__ W_in, const float* __restrict__ Wf,
                        const float* __restrict__ Wa, const float* __restrict__ W_o1,
                        const float* __restrict__ W_o2) {
    int s = blockIdx.x;
    const float* W; int K;
    if (s == 0)      { W = W_in;                 K = 64;  }
    else if (s < 4)  { W = Wf + (s - 1) * 16384; K = 128; }
    else if (s < 7)  { W = Wa + (s - 4) * 16384; K = 128; }
    else if (s == 7) { W = W_o1;                 K = 128; }
    else             { W = W_o2;                 K = 128; }
    int total = 128 * (K / 2);
    for (int idx = threadIdx.x; idx < total; idx += 256) {
        int n = idx & 127, k2 = idx >> 7;         // k-pair index
        int k = 2 * k2;
        float v0 = W[k * 128 + n];
        float v1 = W[(k + 1) * 128 + n];
        unsigned hi, lo; split2(v0, v1, hi, lo);
        int kt = k2 >> 3, rr = k2 & 7;
        int tig = rr & 3, half = rr >> 2;
        int dst = ((kt * 4 + tig) * 128 + n) * 2 + half;
        g_Wpre[(s * 2 + 0) * 8192 + dst] = hi;
        g_Wpre[(s * 2 + 1) * 8192 + dst] = lo;
    }
}

// ---------------- split-bf16 tensor-core GEMM, M-tile 128 ------------------
// C[M,128] = A[M,K] @ W[K,128]; 3-term split (hi*hi + hi*lo + lo*hi).
// B staged as paired uint2 (rows tig / tig+4 adjacent): 2x LDS.64 per j-step.
// EPI: 0 = +bias, 1 = sigmoid, 2 = *Mul, 3 = *Mul^2
// WH: write fp16 g_YH; WF: write fp32 C; STATS: per-block BN partials.
template <int K, int EPI, int WH, int WF, int STATS>
__global__ void __launch_bounds__(256, 2)
k_gemm(const float* __restrict__ A, const uint2* __restrict__ BH2,
       const uint2* __restrict__ BL2, const float* __restrict__ bias,
       const float* __restrict__ Mm, float* __restrict__ C) {
    constexpr int NT = K / 16;                // k tiles
    constexpr int PR = 4 * NT;                // paired rows per plane
    extern __shared__ uint2 smem_p[];
    uint2 (*Bs2h)[132] = reinterpret_cast<uint2(*)[132]>(smem_p);
    uint2 (*Bs2l)[132] = reinterpret_cast<uint2(*)[132]>(smem_p + PR * 132);

    const int tid    = threadIdx.x;
    const int lane   = tid & 31;
    const int warp   = tid >> 5;
    const int bm     = blockIdx.x * 128;
    const int warp_m = (warp >> 1) * 32;
    const int warp_n = (warp & 1) * 64;
    const int grp    = lane >> 2;
    const int tig    = lane & 3;

    // ---- stage B: pure uint4 copy of pre-paired weights ------------------
    for (int idx = tid; idx < PR * 64; idx += 256) {
        int r = idx >> 6, c2 = (idx & 63) * 2;
        *(uint4*)&Bs2h[r][c2] = *(const uint4*)(BH2 + r * 128 + c2);
        *(uint4*)&Bs2l[r][c2] = *(const uint4*)(BL2 + r * 128 + c2);
    }

    // A fragment row pointers: rows r = 2t + h -> warp_m + 16t + 8h + grp
    const float* arow[4];
    bool avld[4];
#pragma unroll
    for (int r = 0; r < 4; r++) {
        int row = bm + warp_m + 16 * (r >> 1) + 8 * (r & 1) + grp;
        avld[r] = row < Nn;
        arow[r] = A + (size_t)(avld[r] ? row : 0) * K + 2 * tig;
    }

    float acc[2][8][4];
#pragma unroll
    for (int t = 0; t < 2; t++)
#pragma unroll
        for (int j = 0; j < 8; j++)
#pragma unroll
            for (int i = 0; i < 4; i++) acc[t][j][i] = 0.f;

    // prefetch ktile 0: 4 rows x 2 kpair-segments (p: +0 / +8 floats)
    float2 pv[4][2];
#pragma unroll
    for (int r = 0; r < 4; r++)
#pragma unroll
        for (int p = 0; p < 2; p++)
            pv[r][p] = avld[r] ? *(const float2*)(arow[r] + 8 * p)
                               : make_float2(0.f, 0.f);

    __syncthreads();   // B ready; no further barriers until epilogue

#pragma unroll
    for (int kt = 0; kt < NT; kt++) {
        unsigned ahi[2][4], alo[2][4];
#pragma unroll
        for (int t = 0; t < 2; t++)
#pragma unroll
            for (int h = 0; h < 2; h++)
#pragma unroll
                for (int p = 0; p < 2; p++)
                    split2(pv[2 * t + h][p].x, pv[2 * t + h][p].y,
                           ahi[t][h + 2 * p], alo[t][h + 2 * p]);
        if (kt + 1 < NT) {
#pragma unroll
            for (int r = 0; r < 4; r++)
#pragma unroll
                for (int p = 0; p < 2; p++)
                    pv[r][p] = avld[r]
                        ? *(const float2*)(arow[r] + 16 * (kt + 1) + 8 * p)
                        : make_float2(0.f, 0.f);
        }

        const int brow = kt * 4 + tig;
#pragma unroll
        for (int j = 0; j < 8; j++) {
            int n = warp_n + 8 * j + grp;
            uint2 bh = Bs2h[brow][n];
            uint2 bl = Bs2l[brow][n];
#pragma unroll
            for (int t = 0; t < 2; t++) {
                MMA_BF16(acc[t][j], ahi[t], bh.x, bh.y);
                MMA_BF16(acc[t][j], ahi[t], bl.x, bl.y);
                MMA_BF16(acc[t][j], alo[t], bh.x, bh.y);
            }
        }
    }

    // ---- epilogue (+ optional fused BN stats partials) -------------------
    float* sred = (float*)smem_p;
    if (STATS) __syncthreads();

#pragma unroll
    for (int j = 0; j < 8; j++) {
        int col = warp_n + 8 * j + 2 * tig;
        float s0 = 0.f, s1 = 0.f, q0 = 0.f, q1 = 0.f;
#pragma unroll
        for (int t = 0; t < 2; t++) {
#pragma unroll
            for (int h = 0; h < 2; h++) {
                int row = bm + warp_m + 16 * t + grp + h * 8;
                if (row >= Nn) continue;
                float v0 = acc[t][j][h * 2 + 0];
                float v1 = acc[t][j][h * 2 + 1];
                if (EPI == 0) {
                    v0 += bias[col]; v1 += bias[col + 1];
                } else if (EPI == 1) {
                    v0 = 1.f / (1.f + __expf(-v0));
                    v1 = 1.f / (1.f + __expf(-v1));
                } else if (EPI == 2) {
                    float2 m = *(const float2*)(Mm + (size_t)row * 128 + col);
                    v0 *= m.x; v1 *= m.y;
                } else if (EPI == 3) {
                    float2 m = *(const float2*)(Mm + (size_t)row * 128 + col);
                    v0 *= m.x * m.x; v1 *= m.y * m.y;
                }
                if (WF) {
                    float2 o; o.x = v0; o.y = v1;
                    *(float2*)(C + (size_t)row * 128 + col) = o;
                }
                if (WH) {
                    *(__half2*)(g_YH + (size_t)row * 128 + col) =
                        __floats2half2_rn(v0, v1);
                }
                if (STATS) {
                    s0 += v0; q0 = fmaf(v0, v0, q0);
                    s1 += v1; q1 = fmaf(v1, v1, q1);
                }
            }
        }
        if (STATS) {
#pragma unroll
            for (int msk = 4; msk <= 16; msk <<= 1) {
                s0 += __shfl_xor_sync(0xffffffffu, s0, msk);
                s1 += __shfl_xor_sync(0xffffffffu, s1, msk);
                q0 += __shfl_xor_sync(0xffffffffu, q0, msk);
                q1 += __shfl_xor_sync(0xffffffffu, q1, msk);
            }
            if (grp == 0) {
                int base = ((warp * 8 + j) * 4 + tig) * 2;
                sred[base + 0]       = s0;
                sred[base + 1]       = s1;
                sred[512 + base + 0] = q0;
                sred[512 + base + 1] = q1;
            }
        }
    }
    if (STATS) {
        __syncthreads();
        if (tid < 128) {
            int p  = tid >> 6;
            int rm = tid & 63;
            int j  = rm >> 3;
            int tg = (rm & 7) >> 1;
            int b  = tid & 1;
            float s = 0.f, q = 0.f;
#pragma unroll
            for (int i = 0; i < 4; i++) {
                int w = p + 2 * i;
                int base = ((w * 8 + j) * 4 + tg) * 2 + b;
                s += sred[base];
                q += sred[512 + base];
            }
            g_part[blockIdx.x * 256 + tid]       = s;
            g_part[blockIdx.x * 256 + 128 + tid] = q;
        }
    }
}

// ---------------- graph preprocessing ----------------
__global__ void k_zero_counts() {
    int i = blockIdx.x * blockDim.x + threadIdx.x;
    if (i < Nn) { g_deg[i] = 0; g_rowcnt[i] = 0; }
}

__global__ void k_detect(const int* __restrict__ ei) {
    if (threadIdx.x == 0 && blockIdx.x == 0) {
        int all0 = 1;
        for (int i = 0; i < 32; i++) {
            if (ei[2 * i + 1] != 0) { all0 = 0; break; }
        }
        g_is64 = all0;
    }
}

__global__ void k_hist(const void* __restrict__ eiv) {
    int e = blockIdx.x * blockDim.x + threadIdx.x;
    if (e >= Ee) return;
    int r, c;
    if (g_is64) {
        const long long* p = (const long long*)eiv;
        r = (int)p[e]; c = (int)p[Ee + e];
    } else {
        const int* p = (const int*)eiv;
        r = p[e]; c = p[Ee + e];
    }
    if (r != c) {
        atomicAdd(&g_deg[c], 1);
        atomicAdd(&g_rowcnt[r], 1);
    }
}

__global__ void k_dinv() {
    int i = blockIdx.x * blockDim.x + threadIdx.x;
    if (i < Nn) g_dinv[i] = rsqrtf((float)(g_deg[i] + 1));
}

__global__ void k_scan() {
    __shared__ int s[1024];
    const int t  = threadIdx.x;
    const int CH = (Nn + 1023) / 1024;
    int base = t * CH;
    int sum = 0;
    for (int i = 0; i < CH; i++) {
        int idx = base + i;
        if (idx < Nn) sum += g_rowcnt[idx];
    }
    s[t] = sum;
    __syncthreads();
    for (int off = 1; off < 1024; off <<= 1) {
        int v = (t >= off) ? s[t - off] : 0;
        __syncthreads();
        s[t] += v;
        __syncthreads();
    }
    int run = s[t] - sum;
    for (int i = 0; i < CH; i++) {
        int idx = base + i;
        if (idx < Nn) {
            g_rowptr[idx] = run;
            g_cursor[idx] = run;
            run += g_rowcnt[idx];
        }
    }
    if (t == 1023) g_rowptr[Nn] = s[1023];
}

__global__ void k_fill(const void* __restrict__ eiv) {
    int e = blockIdx.x * blockDim.x + threadIdx.x;
    if (e >= Ee) return;
    int r, c;
    if (g_is64) {
        const long long* p = (const long long*)eiv;
        r = (int)p[e]; c = (int)p[Ee + e];
    } else {
        const int* p = (const int*)eiv;
        r = p[e]; c = p[Ee + e];
    }
    if (r != c) {
        int pos = atomicAdd(&g_cursor[r], 1);
        g_ccol[pos] = c;
        g_cw[pos]   = g_dinv[r] * g_dinv[c];
    }
}

// ---------------- SpMM: fp16 gather (g_YH), fp32 accumulate/output ---------
__global__ void __launch_bounds__(256) k_spmm(float* __restrict__ out) {
    int w    = (blockIdx.x * 256 + threadIdx.x) >> 5;
    int lane = threadIdx.x & 31;
    if (w >= Nn) return;
    int s = g_rowptr[w], e = g_rowptr[w + 1];
    const uint2* yh = (const uint2*)g_YH;   // 4 halfs per uint2; row stride 32
    float4 acc = make_float4(0.f, 0.f, 0.f, 0.f);
    int i = s;
    for (; i + 3 < e; i += 4) {
        int   c0 = __ldg(&g_ccol[i]);
        int   c1 = __ldg(&g_ccol[i + 1]);
        int   c2 = __ldg(&g_ccol[i + 2]);
        int   c3 = __ldg(&g_ccol[i + 3]);
        float w0 = __ldg(&g_cw[i]);
        float w1 = __ldg(&g_cw[i + 1]);
        float w2 = __ldg(&g_cw[i + 2]);
        float w3 = __ldg(&g_cw[i + 3]);
        uint2 r0 = __ldg(&yh[(size_t)c0 * 32 + lane]);
        uint2 r1 = __ldg(&yh[(size_t)c1 * 32 + lane]);
        uint2 r2 = __ldg(&yh[(size_t)c2 * 32 + lane]);
        uint2 r3 = __ldg(&yh[(size_t)c3 * 32 + lane]);
        float2 a0 = __half22float2(*(__half2*)&r0.x), b0 = __half22float2(*(__half2*)&r0.y);
        float2 a1 = __half22float2(*(__half2*)&r1.x), b1 = __half22float2(*(__half2*)&r1.y);
        float2 a2 = __half22float2(*(__half2*)&r2.x), b2 = __half22float2(*(__half2*)&r2.y);
        float2 a3 = __half22float2(*(__half2*)&r3.x), b3 = __half22float2(*(__half2*)&r3.y);
        acc.x = fmaf(w0, a0.x, acc.x); acc.y = fmaf(w0, a0.y, acc.y);
        acc.z = fmaf(w0, b0.x, acc.z); acc.w = fmaf(w0, b0.y, acc.w);
        acc.x = fmaf(w1, a1.x, acc.x); acc.y = fmaf(w1, a1.y, acc.y);
        acc.z = fmaf(w1, b1.x, acc.z); acc.w = fmaf(w1, b1.y, acc.w);
        acc.x = fmaf(w2, a2.x, acc.x); acc.y = fmaf(w2, a2.y, acc.y);
        acc.z = fmaf(w2, b2.x, acc.z); acc.w = fmaf(w2, b2.y, acc.w);
        acc.x = fmaf(w3, a3.x, acc.x); acc.y = fmaf(w3, a3.y, acc.y);
        acc.z = fmaf(w3, b3.x, acc.z); acc.w = fmaf(w3, b3.y, acc.w);
    }
    for (; i < e; i++) {
        int   c0 = __ldg(&g_ccol[i]);
        float w0 = __ldg(&g_cw[i]);
        uint2 r0 = __ldg(&yh[(size_t)c0 * 32 + lane]);
        float2 a0 = __half22float2(*(__half2*)&r0.x), b0 = __half22float2(*(__half2*)&r0.y);
        acc.x = fmaf(w0, a0.x, acc.x); acc.y = fmaf(w0, a0.y, acc.y);
        acc.z = fmaf(w0, b0.x, acc.z); acc.w = fmaf(w0, b0.y, acc.w);
    }
    // self loop: weight = dinv^2
    float sw = g_dinv[w]; sw *= sw;
    uint2 rs = yh[(size_t)w * 32 + lane];
    float2 as = __half22float2(*(__half2*)&rs.x), bs = __half22float2(*(__half2*)&rs.y);
    acc.x = fmaf(sw, as.x, acc.x); acc.y = fmaf(sw, as.y, acc.y);
    acc.z = fmaf(sw, bs.x, acc.z); acc.w = fmaf(sw, bs.y, acc.w);
    ((float4*)out)[(size_t)w * 32 + lane] = acc;
}

// ---------------- BN param computation from partials ----------------------
__global__ void k_stats2(const float* __restrict__ g, const float* __restrict__ bt,
                         int nb) {
    int c = threadIdx.x;
    float s = 0.f, q = 0.f;
    for (int b = 0; b < nb; b++) {
        s += g_part[b * 256 + c];
        q += g_part[b * 256 + 128 + c];
    }
    float mean = s / (float)Nn;
    float var  = q / (float)Nn - mean * mean;
    float a = g[c] * rsqrtf(var + EPSV);
    g_alpha[c] = a;
    g_beta[c]  = bt[c] - mean * a;
}

// ---------------- BN apply (+ReLU, optional residual) ---------------------
template <int ADD>
__global__ void k_bn(const float* __restrict__ src, const float* __restrict__ prevIn,
                     float* __restrict__ dst) {
    int i = blockIdx.x * blockDim.x + threadIdx.x;
    if (i >= Nn * 32) return;
    int c = (i & 31) * 4;
    float4 v = ((const float4*)src)[i];
    v.x = fmaxf(fmaf(g_alpha[c + 0], v.x, g_beta[c + 0]), 0.f);
    v.y = fmaxf(fmaf(g_alpha[c + 1], v.y, g_beta[c + 1]), 0.f);
    v.z = fmaxf(fmaf(g_alpha[c + 2], v.z, g_beta[c + 2]), 0.f);
    v.w = fmaxf(fmaf(g_alpha[c + 3], v.w, g_beta[c + 3]), 0.f);
    if (ADD) {
        float4 p = ((const float4*)prevIn)[i];
        v.x += p.x; v.y += p.y; v.z += p.z; v.w += p.w;
    }
    ((float4*)dst)[i] = v;
}

// ---------------- launch ----------------
static int smb(int K) { return 2 * (4 * (K / 16)) * 132 * 8; }   // 2 planes x PR x 132 uint2

extern "C" void kernel_launch(void* const* d_in, const int* in_sizes, int n_in,
                              void* d_out, int out_size) {
    const float* x     = (const float*)d_in[0];
    const void*  ei    = d_in[1];
    const float* W_in  = (const float*)d_in[2];
    const float* b_in  = (const float*)d_in[3];
    const float* gin   = (const float*)d_in[4];
    const float* btin  = (const float*)d_in[5];
    const float* Wf    = (const float*)d_in[6];
    const float* Wa    = (const float*)d_in[7];
    const float* gnorm = (const float*)d_in[8];
    const float* btnorm= (const float*)d_in[9];
    const float* W_o1  = (const float*)d_in[10];
    const float* b_o1  = (const float*)d_in[11];
    const float* g_o   = (const float*)d_in[12];
    const float* bt_o  = (const float*)d_in[13];
    const float* W_o2  = (const float*)d_in[14];
    const float* b_o2  = (const float*)d_in[15];
    float* out = (float*)d_out;

    float *T, *H, *Y0, *PREV;
    unsigned* wpre;
    cudaGetSymbolAddress((void**)&T,    g_T);
    cudaGetSymbolAddress((void**)&H,    g_H);
    cudaGetSymbolAddress((void**)&Y0,   g_Y0);
    cudaGetSymbolAddress((void**)&PREV, g_PREV);
    cudaGetSymbolAddress((void**)&wpre, g_Wpre);
    auto wh = [&](int s) { return (const uint2*)(wpre + (size_t)(s * 2 + 0) * 8192); };
    auto wl = [&](int s) { return (const uint2*)(wpre + (size_t)(s * 2 + 1) * 8192); };

    // instantiations: <K, EPI, WH, WF, STATS>
    cudaFuncSetAttribute(k_gemm<64, 0, 0, 1, 1>,  cudaFuncAttributeMaxDynamicSharedMemorySize, smb(64));
    cudaFuncSetAttribute(k_gemm<128, 1, 1, 1, 0>, cudaFuncAttributeMaxDynamicSharedMemorySize, smb(128));
    cudaFuncSetAttribute(k_gemm<128, 3, 1, 0, 0>, cudaFuncAttributeMaxDynamicSharedMemorySize, smb(128));
    cudaFuncSetAttribute(k_gemm<128, 2, 0, 1, 1>, cudaFuncAttributeMaxDynamicSharedMemorySize, smb(128));
    cudaFuncSetAttribute(k_gemm<128, 2, 0, 1, 0>, cudaFuncAttributeMaxDynamicSharedMemorySize, smb(128));
    cudaFuncSetAttribute(k_gemm<128, 0, 0, 1, 1>, cudaFuncAttributeMaxDynamicSharedMemorySize, smb(128));
    cudaFuncSetAttribute(k_gemm<128, 0, 0, 1, 0>, cudaFuncAttributeMaxDynamicSharedMemorySize, smb(128));

    const int NB  = (Nn + 255) / 256;
    const int EB  = (Ee + 255) / 256;
    const int EWB = (Nn * 32 + 255) / 256;

    k_zero_counts<<<NB, 256>>>();                                        // 0
    k_prepw<<<9, 256>>>(W_in, Wf, Wa, W_o1, W_o2);                       // 1
    k_detect<<<1, 32>>>((const int*)ei);                                 // 2
    k_gemm<64, 0, 0, 1, 1><<<GB1, 256, smb(64)>>>(
        x, wh(0), wl(0), b_in, nullptr, T);                              // 3 <- profiled
    k_hist<<<EB, 256>>>(ei);                                             // 4
    k_dinv<<<NB, 256>>>();                                               // 5
    k_scan<<<1, 1024>>>();                                               // 6
    k_fill<<<EB, 256>>>(ei);                                             // 7
    k_stats2<<<1, 128>>>(gin, btin, GB1);                                // 8
    k_bn<0><<<EWB, 256>>>(T, nullptr, PREV);                             // 9

    for (int l = 0; l < 3; l++) {
        // y0 = sigmoid(PREV @ Wf): fp32 Y0 + fp16 g_YH
        k_gemm<128, 1, 1, 1, 0><<<GB1, 256, smb(128)>>>(
            PREV, wh(1 + l), wl(1 + l), nullptr, nullptr, Y0);
        k_spmm<<<EWB, 256>>>(T);     // T = A_hat @ y0 (fp16 gather)
        // y = y0^2 * (T @ Wa): fp16 only (fp32 output dead)
        k_gemm<128, 3, 1, 0, 0><<<GB1, 256, smb(128)>>>(
            T, wh(4 + l), wl(4 + l), nullptr, Y0, nullptr);
        k_spmm<<<EWB, 256>>>(T);     // T = A_hat @ y
        if (l < 2) {
            // h = y0 * (T @ Wa) + fused BN stats
            k_gemm<128, 2, 0, 1, 1><<<GB1, 256, smb(128)>>>(
                T, wh(4 + l), wl(4 + l), nullptr, Y0, H);
            k_stats2<<<1, 128>>>(gnorm + l * 128, btnorm + l * 128, GB1);
            k_bn<1><<<EWB, 256>>>(H, PREV, PREV);
        } else {
            k_gemm<128, 2, 0, 1, 0><<<GB1, 256, smb(128)>>>(
                T, wh(4 + l), wl(4 + l), nullptr, Y0, H);
        }
    }

    // output encoder: Linear -> BN -> ReLU -> Linear
    k_gemm<128, 0, 0, 1, 1><<<GB1, 256, smb(128)>>>(
        H, wh(7), wl(7), b_o1, nullptr, T);
    k_stats2<<<1, 128>>>(g_o, bt_o, GB1);
    k_bn<0><<<EWB, 256>>>(T, nullptr, Y0);
    k_gemm<128, 0, 0, 1, 0><<<GB1, 256, smb(128)>>>(
        Y0, wh(8), wl(8), b_o2, nullptr, out);
}

// round 17
// speedup vs baseline: 1.0316x; 1.0119x over previous
#include <cuda_runtime.h>
#include <cuda_fp16.h>
#include <cstdint>
#include <math.h>

// ---------------- problem constants ----------------
#define Nn   50000
#define Ee   800000
#define FEAT 64
#define HID  128
#define EPSV 1e-5f
#define GB1 ((Nn + 127) / 128)    // 391 GEMM blocks (M-tile 128)

// ---------------- static device scratch (no allocs allowed) ----------------
__device__ float  g_T   [Nn * HID];
__device__ float  g_H   [Nn * HID];
__device__ float  g_Y0  [Nn * HID];
__device__ float  g_PREV[Nn * HID];
__device__ __half g_XH  [Nn * FEAT];   // fp16 input features
__device__ __half g_YH  [Nn * HID];    // fp16 SpMM gather matrix
__device__ __half g_TH  [Nn * HID];    // fp16 SpMM#1 output (EPI=3 GEMM A)

__device__ int   g_deg   [Nn];
__device__ int   g_rowcnt[Nn];
__device__ int   g_rowptr[Nn + 1];
__device__ int   g_cursor[Nn];
__device__ float g_dinv  [Nn];
__device__ int   g_ccol  [Ee];
__device__ float g_cw    [Ee];

__device__ float g_part [GB1 * 256];
__device__ float g_alpha[HID];
__device__ float g_beta [HID];
__device__ int   g_is64;

// pre-converted weights: 9 slots x {hi,lo} x 8192 words (fp16x2).
// paired layout: word pair[(kt*4+tig)*128+n][half] covers k2 = kt*8+tig (+4)
__device__ unsigned g_Wpre[9 * 2 * 8192];

// ---------------- helpers ----------------
__device__ __forceinline__ void hsplit2(float x, float y, unsigned& hi, unsigned& lo) {
    __half2 h = __floats2half2_rn(x, y);
    float rx = x - __low2float(h);
    float ry = y - __high2float(h);
    __half2 l = __floats2half2_rn(rx, ry);
    hi = *(unsigned*)&h;
    lo = *(unsigned*)&l;
}

#define MMA_F16(C, A, B0, B1)                                                 \
    asm volatile(                                                             \
        "mma.sync.aligned.m16n8k16.row.col.f32.f16.f16.f32 "                  \
        "{%0,%1,%2,%3}, {%4,%5,%6,%7}, {%8,%9}, {%0,%1,%2,%3};"               \
        : "+f"((C)[0]), "+f"((C)[1]), "+f"((C)[2]), "+f"((C)[3])              \
        : "r"((A)[0]), "r"((A)[1]), "r"((A)[2]), "r"((A)[3]),                 \
          "r"(B0), "r"(B1))

// ---------------- weight pre-conversion -> paired fp16 hi/lo ---------------
__global__ void k_prepw(const float* __restrict__ W_in, const float* __restrict__ Wf,
                        const float* __restrict__ Wa, const float* __restrict__ W_o1,
                        const float* __restrict__ W_o2) {
    int s = blockIdx.x;
    const float* W; int K;
    if (s == 0)      { W = W_in;                 K = 64;  }
    else if (s < 4)  { W = Wf + (s - 1) * 16384; K = 128; }
    else if (s < 7)  { W = Wa + (s - 4) * 16384; K = 128; }
    else if (s == 7) { W = W_o1;                 K = 128; }
    else             { W = W_o2;                 K = 128; }
    int total = 128 * (K / 2);
    for (int idx = threadIdx.x; idx < total; idx += 256) {
        int n = idx & 127, k2 = idx >> 7;
        int k = 2 * k2;
        float v0 = W[k * 128 + n];
        float v1 = W[(k + 1) * 128 + n];
        unsigned hi, lo; hsplit2(v0, v1, hi, lo);
        int kt = k2 >> 3, rr = k2 & 7;
        int tig = rr & 3, half = rr >> 2;
        int dst = ((kt * 4 + tig) * 128 + n) * 2 + half;
        g_Wpre[(s * 2 + 0) * 8192 + dst] = hi;
        g_Wpre[(s * 2 + 1) * 8192 + dst] = lo;
    }
}

// ---------------- x -> fp16 ----------------
__global__ void k_cvt(const float* __restrict__ x) {
    int i = blockIdx.x * blockDim.x + threadIdx.x;   // float4 index
    if (i >= Nn * (FEAT / 4)) return;
    float4 v = ((const float4*)x)[i];
    __half2 a = __floats2half2_rn(v.x, v.y);
    __half2 b = __floats2half2_rn(v.z, v.w);
    uint2 o; o.x = *(unsigned*)&a; o.y = *(unsigned*)&b;
    ((uint2*)g_XH)[i] = o;
}

// ---------------- fp16 tensor-core GEMM, M-tile 128 ------------------------
// C[M,128] = A[M,K] @ W[K,128]; B 2-term fp16 (hi+lo), paired SMEM layout.
// AFMT 0: A fp32, in-loop fp16 hi/lo split -> 3 MMAs (ah*bh + ah*bl + al*bh).
// AFMT 1: A fp16 single plane -> 2 MMAs (a*bh + a*bl), 2-deep prefetch.
// EPI: 0 = +bias, 1 = sigmoid, 2 = *Mul, 3 = *Mul^2
// WH: write fp16 Hout; WF: write fp32 C; STATS: per-block BN partials.
template <int K, int EPI, int AFMT, int WH, int WF, int STATS>
__global__ void __launch_bounds__(256, 2)
k_gemm(const float* __restrict__ A, const __half* __restrict__ AH,
       const uint2* __restrict__ BH2, const uint2* __restrict__ BL2,
       const float* __restrict__ bias, const float* __restrict__ Mm,
       float* __restrict__ C, __half* __restrict__ Hout) {
    constexpr int NT = K / 16;                // k tiles
    constexpr int PR = 4 * NT;                // paired rows per plane
    extern __shared__ uint2 smem_p[];
    uint2 (*Bs2h)[132] = reinterpret_cast<uint2(*)[132]>(smem_p);
    uint2 (*Bs2l)[132] = reinterpret_cast<uint2(*)[132]>(smem_p + PR * 132);

    const int tid    = threadIdx.x;
    const int lane   = tid & 31;
    const int warp   = tid >> 5;
    const int bm     = blockIdx.x * 128;
    const int warp_m = (warp >> 1) * 32;
    const int warp_n = (warp & 1) * 64;
    const int grp    = lane >> 2;
    const int tig    = lane & 3;

    // ---- stage B: pure uint4 copy of pre-paired fp16 weights -------------
    for (int idx = tid; idx < PR * 64; idx += 256) {
        int r = idx >> 6, c2 = (idx & 63) * 2;
        *(uint4*)&Bs2h[r][c2] = *(const uint4*)(BH2 + r * 128 + c2);
        *(uint4*)&Bs2l[r][c2] = *(const uint4*)(BL2 + r * 128 + c2);
    }

    // A row bases: rows r = 2t + h -> warp_m + 16t + 8h + grp
    const float*    arow[4];
    const unsigned* aru[4];
    bool avld[4];
#pragma unroll
    for (int r = 0; r < 4; r++) {
        int row = bm + warp_m + 16 * (r >> 1) + 8 * (r & 1) + grp;
        avld[r] = row < Nn;
        int rr = avld[r] ? row : 0;
        if (AFMT == 0) arow[r] = A + (size_t)rr * K + 2 * tig;
        else           aru[r]  = (const unsigned*)(AH + (size_t)rr * K) + tig;
    }

    float acc[2][8][4];
#pragma unroll
    for (int t = 0; t < 2; t++)
#pragma unroll
        for (int j = 0; j < 8; j++)
#pragma unroll
            for (int i = 0; i < 4; i++) acc[t][j][i] = 0.f;

    // prefetch: AFMT=0 1-deep float2; AFMT=1 2-deep fp16 pairs
    float2   pv[4][2];
    unsigned pa[2][4][2];
    if (AFMT == 0) {
#pragma unroll
        for (int r = 0; r < 4; r++)
#pragma unroll
            for (int p = 0; p < 2; p++)
                pv[r][p] = avld[r] ? *(const float2*)(arow[r] + 8 * p)
                                   : make_float2(0.f, 0.f);
    } else {
#pragma unroll
        for (int st = 0; st < 2; st++)
#pragma unroll
            for (int r = 0; r < 4; r++)
#pragma unroll
                for (int p = 0; p < 2; p++)
                    pa[st][r][p] = (avld[r] && st < NT) ? aru[r][8 * st + 4 * p] : 0u;
    }

    __syncthreads();   // B ready; no further barriers until epilogue

#pragma unroll
    for (int kt = 0; kt < NT; kt++) {
        unsigned ahi[2][4], alo[2][4];
        if (AFMT == 0) {
#pragma unroll
            for (int t = 0; t < 2; t++)
#pragma unroll
                for (int h = 0; h < 2; h++)
#pragma unroll
                    for (int p = 0; p < 2; p++)
                        hsplit2(pv[2 * t + h][p].x, pv[2 * t + h][p].y,
                                ahi[t][h + 2 * p], alo[t][h + 2 * p]);
            if (kt + 1 < NT) {
#pragma unroll
                for (int r = 0; r < 4; r++)
#pragma unroll
                    for (int p = 0; p < 2; p++)
                        pv[r][p] = avld[r]
                            ? *(const float2*)(arow[r] + 16 * (kt + 1) + 8 * p)
                            : make_float2(0.f, 0.f);
            }
        } else {
            const int st = kt & 1;
#pragma unroll
            for (int t = 0; t < 2; t++) {
                ahi[t][0] = pa[st][2 * t + 0][0];
                ahi[t][1] = pa[st][2 * t + 1][0];
                ahi[t][2] = pa[st][2 * t + 0][1];
                ahi[t][3] = pa[st][2 * t + 1][1];
            }
            if (kt + 2 < NT) {
#pragma unroll
                for (int r = 0; r < 4; r++)
#pragma unroll
                    for (int p = 0; p < 2; p++)
                        pa[st][r][p] = avld[r] ? aru[r][8 * (kt + 2) + 4 * p] : 0u;
            }
        }

        const int brow = kt * 4 + tig;
#pragma unroll
        for (int j = 0; j < 8; j++) {
            int n = warp_n + 8 * j + grp;
            uint2 bh = Bs2h[brow][n];
            uint2 bl = Bs2l[brow][n];
#pragma unroll
            for (int t = 0; t < 2; t++) {
                MMA_F16(acc[t][j], ahi[t], bh.x, bh.y);
                MMA_F16(acc[t][j], ahi[t], bl.x, bl.y);
                if (AFMT == 0) MMA_F16(acc[t][j], alo[t], bh.x, bh.y);
            }
        }
    }

    // ---- epilogue (+ optional fused BN stats partials) -------------------
    float* sred = (float*)smem_p;
    if (STATS) __syncthreads();

#pragma unroll
    for (int j = 0; j < 8; j++) {
        int col = warp_n + 8 * j + 2 * tig;
        float s0 = 0.f, s1 = 0.f, q0 = 0.f, q1 = 0.f;
#pragma unroll
        for (int t = 0; t < 2; t++) {
#pragma unroll
            for (int h = 0; h < 2; h++) {
                int row = bm + warp_m + 16 * t + grp + h * 8;
                if (row >= Nn) continue;
                float v0 = acc[t][j][h * 2 + 0];
                float v1 = acc[t][j][h * 2 + 1];
                if (EPI == 0) {
                    v0 += bias[col]; v1 += bias[col + 1];
                } else if (EPI == 1) {
                    v0 = 1.f / (1.f + __expf(-v0));
                    v1 = 1.f / (1.f + __expf(-v1));
                } else if (EPI == 2) {
                    float2 m = *(const float2*)(Mm + (size_t)row * 128 + col);
                    v0 *= m.x; v1 *= m.y;
                } else if (EPI == 3) {
                    float2 m = *(const float2*)(Mm + (size_t)row * 128 + col);
                    v0 *= m.x * m.x; v1 *= m.y * m.y;
                }
                if (WF) {
                    float2 o; o.x = v0; o.y = v1;
                    *(float2*)(C + (size_t)row * 128 + col) = o;
                }
                if (WH) {
                    __half2 hh = __floats2half2_rn(v0, v1);
                    *(__half2*)(Hout + (size_t)row * 128 + col) = hh;
                }
                if (STATS) {
                    s0 += v0; q0 = fmaf(v0, v0, q0);
                    s1 += v1; q1 = fmaf(v1, v1, q1);
                }
            }
        }
        if (STATS) {
#pragma unroll
            for (int msk = 4; msk <= 16; msk <<= 1) {
                s0 += __shfl_xor_sync(0xffffffffu, s0, msk);
                s1 += __shfl_xor_sync(0xffffffffu, s1, msk);
                q0 += __shfl_xor_sync(0xffffffffu, q0, msk);
                q1 += __shfl_xor_sync(0xffffffffu, q1, msk);
            }
            if (grp == 0) {
                int base = ((warp * 8 + j) * 4 + tig) * 2;
                sred[base + 0]       = s0;
                sred[base + 1]       = s1;
                sred[512 + base + 0] = q0;
                sred[512 + base + 1] = q1;
            }
        }
    }
    if (STATS) {
        __syncthreads();
        if (tid < 128) {
            int p  = tid >> 6;
            int rm = tid & 63;
            int j  = rm >> 3;
            int tg = (rm & 7) >> 1;
            int b  = tid & 1;
            float s = 0.f, q = 0.f;
#pragma unroll
            for (int i = 0; i < 4; i++) {
                int w = p + 2 * i;
                int base = ((w * 8 + j) * 4 + tg) * 2 + b;
                s += sred[base];
                q += sred[512 + base];
            }
            g_part[blockIdx.x * 256 + tid]       = s;
            g_part[blockIdx.x * 256 + 128 + tid] = q;
        }
    }
}

// ---------------- graph preprocessing ----------------
__global__ void k_zero_counts() {
    int i = blockIdx.x * blockDim.x + threadIdx.x;
    if (i < Nn) { g_deg[i] = 0; g_rowcnt[i] = 0; }
}

__global__ void k_detect(const int* __restrict__ ei) {
    if (threadIdx.x == 0 && blockIdx.x == 0) {
        int all0 = 1;
        for (int i = 0; i < 32; i++) {
            if (ei[2 * i + 1] != 0) { all0 = 0; break; }
        }
        g_is64 = all0;
    }
}

__global__ void k_hist(const void* __restrict__ eiv) {
    int e = blockIdx.x * blockDim.x + threadIdx.x;
    if (e >= Ee) return;
    int r, c;
    if (g_is64) {
        const long long* p = (const long long*)eiv;
        r = (int)p[e]; c = (int)p[Ee + e];
    } else {
        const int* p = (const int*)eiv;
        r = p[e]; c = p[Ee + e];
    }
    if (r != c) {
        atomicAdd(&g_deg[c], 1);
        atomicAdd(&g_rowcnt[r], 1);
    }
}

__global__ void k_dinv() {
    int i = blockIdx.x * blockDim.x + threadIdx.x;
    if (i < Nn) g_dinv[i] = rsqrtf((float)(g_deg[i] + 1));
}

__global__ void k_scan() {
    __shared__ int s[1024];
    const int t  = threadIdx.x;
    const int CH = (Nn + 1023) / 1024;
    int base = t * CH;
    int sum = 0;
    for (int i = 0; i < CH; i++) {
        int idx = base + i;
        if (idx < Nn) sum += g_rowcnt[idx];
    }
    s[t] = sum;
    __syncthreads();
    for (int off = 1; off < 1024; off <<= 1) {
        int v = (t >= off) ? s[t - off] : 0;
        __syncthreads();
        s[t] += v;
        __syncthreads();
    }
    int run = s[t] - sum;
    for (int i = 0; i < CH; i++) {
        int idx = base + i;
        if (idx < Nn) {
            g_rowptr[idx] = run;
            g_cursor[idx] = run;
            run += g_rowcnt[idx];
        }
    }
    if (t == 1023) g_rowptr[Nn] = s[1023];
}

__global__ void k_fill(const void* __restrict__ eiv) {
    int e = blockIdx.x * blockDim.x + threadIdx.x;
    if (e >= Ee) return;
    int r, c;
    if (g_is64) {
        const long long* p = (const long long*)eiv;
        r = (int)p[e]; c = (int)p[Ee + e];
    } else {
        const int* p = (const int*)eiv;
        r = p[e]; c = p[Ee + e];
    }
    if (r != c) {
        int pos = atomicAdd(&g_cursor[r], 1);
        g_ccol[pos] = c;
        g_cw[pos]   = g_dinv[r] * g_dinv[c];
    }
}

// ---------------- SpMM: fp16 gather (g_YH) -> fp16 or fp32 output ----------
template <int HOUT>
__global__ void __launch_bounds__(256) k_spmm(float* __restrict__ outF,
                                              __half* __restrict__ outH) {
    int w    = (blockIdx.x * 256 + threadIdx.x) >> 5;
    int lane = threadIdx.x & 31;
    if (w >= Nn) return;
    int s = g_rowptr[w], e = g_rowptr[w + 1];
    const uint2* yh = (const uint2*)g_YH;   // 4 halfs per uint2; row stride 32
    float4 acc = make_float4(0.f, 0.f, 0.f, 0.f);
    int i = s;
    for (; i + 3 < e; i += 4) {
        int   c0 = __ldg(&g_ccol[i]);
        int   c1 = __ldg(&g_ccol[i + 1]);
        int   c2 = __ldg(&g_ccol[i + 2]);
        int   c3 = __ldg(&g_ccol[i + 3]);
        float w0 = __ldg(&g_cw[i]);
        float w1 = __ldg(&g_cw[i + 1]);
        float w2 = __ldg(&g_cw[i + 2]);
        float w3 = __ldg(&g_cw[i + 3]);
        uint2 r0 = __ldg(&yh[(size_t)c0 * 32 + lane]);
        uint2 r1 = __ldg(&yh[(size_t)c1 * 32 + lane]);
        uint2 r2 = __ldg(&yh[(size_t)c2 * 32 + lane]);
        uint2 r3 = __ldg(&yh[(size_t)c3 * 32 + lane]);
        float2 a0 = __half22float2(*(__half2*)&r0.x), b0 = __half22float2(*(__half2*)&r0.y);
        float2 a1 = __half22float2(*(__half2*)&r1.x), b1 = __half22float2(*(__half2*)&r1.y);
        float2 a2 = __half22float2(*(__half2*)&r2.x), b2 = __half22float2(*(__half2*)&r2.y);
        float2 a3 = __half22float2(*(__half2*)&r3.x), b3 = __half22float2(*(__half2*)&r3.y);
        acc.x = fmaf(w0, a0.x, acc.x); acc.y = fmaf(w0, a0.y, acc.y);
        acc.z = fmaf(w0, b0.x, acc.z); acc.w = fmaf(w0, b0.y, acc.w);
        acc.x = fmaf(w1, a1.x, acc.x); acc.y = fmaf(w1, a1.y, acc.y);
        acc.z = fmaf(w1, b1.x, acc.z); acc.w = fmaf(w1, b1.y, acc.w);
        acc.x = fmaf(w2, a2.x, acc.x); acc.y = fmaf(w2, a2.y, acc.y);
        acc.z = fmaf(w2, b2.x, acc.z); acc.w = fmaf(w2, b2.y, acc.w);
        acc.x = fmaf(w3, a3.x, acc.x); acc.y = fmaf(w3, a3.y, acc.y);
        acc.z = fmaf(w3, b3.x, acc.z); acc.w = fmaf(w3, b3.y, acc.w);
    }
    for (; i < e; i++) {
        int   c0 = __ldg(&g_ccol[i]);
        float w0 = __ldg(&g_cw[i]);
        uint2 r0 = __ldg(&yh[(size_t)c0 * 32 + lane]);
        float2 a0 = __half22float2(*(__half2*)&r0.x), b0 = __half22float2(*(__half2*)&r0.y);
        acc.x = fmaf(w0, a0.x, acc.x); acc.y = fmaf(w0, a0.y, acc.y);
        acc.z = fmaf(w0, b0.x, acc.z); acc.w = fmaf(w0, b0.y, acc.w);
    }
    // self loop: weight = dinv^2
    float sw = g_dinv[w]; sw *= sw;
    uint2 rs = yh[(size_t)w * 32 + lane];
    float2 as = __half22float2(*(__half2*)&rs.x), bs = __half22float2(*(__half2*)&rs.y);
    acc.x = fmaf(sw, as.x, acc.x); acc.y = fmaf(sw, as.y, acc.y);
    acc.z = fmaf(sw, bs.x, acc.z); acc.w = fmaf(sw, bs.y, acc.w);
    if (HOUT) {
        __half2 o0 = __floats2half2_rn(acc.x, acc.y);
        __half2 o1 = __floats2half2_rn(acc.z, acc.w);
        uint2 o; o.x = *(unsigned*)&o0; o.y = *(unsigned*)&o1;
        ((uint2*)outH)[(size_t)w * 32 + lane] = o;
    } else {
        ((float4*)outF)[(size_t)w * 32 + lane] = acc;
    }
}

// ---------------- BN param computation from partials ----------------------
__global__ void k_stats2(const float* __restrict__ g, const float* __restrict__ bt,
                         int nb) {
    int c = threadIdx.x;
    float s = 0.f, q = 0.f;
    for (int b = 0; b < nb; b++) {
        s += g_part[b * 256 + c];
        q += g_part[b * 256 + 128 + c];
    }
    float mean = s / (float)Nn;
    float var  = q / (float)Nn - mean * mean;
    float a = g[c] * rsqrtf(var + EPSV);
    g_alpha[c] = a;
    g_beta[c]  = bt[c] - mean * a;
}

// ---------------- BN apply (+ReLU, optional residual) ---------------------
template <int ADD>
__global__ void k_bn(const float* __restrict__ src, const float* __restrict__ prevIn,
                     float* __restrict__ dst) {
    int i = blockIdx.x * blockDim.x + threadIdx.x;
    if (i >= Nn * 32) return;
    int c = (i & 31) * 4;
    float4 v = ((const float4*)src)[i];
    v.x = fmaxf(fmaf(g_alpha[c + 0], v.x, g_beta[c + 0]), 0.f);
    v.y = fmaxf(fmaf(g_alpha[c + 1], v.y, g_beta[c + 1]), 0.f);
    v.z = fmaxf(fmaf(g_alpha[c + 2], v.z, g_beta[c + 2]), 0.f);
    v.w = fmaxf(fmaf(g_alpha[c + 3], v.w, g_beta[c + 3]), 0.f);
    if (ADD) {
        float4 p = ((const float4*)prevIn)[i];
        v.x += p.x; v.y += p.y; v.z += p.z; v.w += p.w;
    }
    ((float4*)dst)[i] = v;
}

// ---------------- launch ----------------
static int smb(int K) { return 2 * (4 * (K / 16)) * 132 * 8; }

extern "C" void kernel_launch(void* const* d_in, const int* in_sizes, int n_in,
                              void* d_out, int out_size) {
    const float* x     = (const float*)d_in[0];
    const void*  ei    = d_in[1];
    const float* W_in  = (const float*)d_in[2];
    const float* b_in  = (const float*)d_in[3];
    const float* gin   = (const float*)d_in[4];
    const float* btin  = (const float*)d_in[5];
    const float* Wf    = (const float*)d_in[6];
    const float* Wa    = (const float*)d_in[7];
    const float* gnorm = (const float*)d_in[8];
    const float* btnorm= (const float*)d_in[9];
    const float* W_o1  = (const float*)d_in[10];
    const float* b_o1  = (const float*)d_in[11];
    const float* g_o   = (const float*)d_in[12];
    const float* bt_o  = (const float*)d_in[13];
    const float* W_o2  = (const float*)d_in[14];
    const float* b_o2  = (const float*)d_in[15];
    float* out = (float*)d_out;

    float *T, *H, *Y0, *PREV;
    __half *XH, *YH, *TH;
    unsigned* wpre;
    cudaGetSymbolAddress((void**)&T,    g_T);
    cudaGetSymbolAddress((void**)&H,    g_H);
    cudaGetSymbolAddress((void**)&Y0,   g_Y0);
    cudaGetSymbolAddress((void**)&PREV, g_PREV);
    cudaGetSymbolAddress((void**)&XH,   g_XH);
    cudaGetSymbolAddress((void**)&YH,   g_YH);
    cudaGetSymbolAddress((void**)&TH,   g_TH);
    cudaGetSymbolAddress((void**)&wpre, g_Wpre);
    auto wh = [&](int s) { return (const uint2*)(wpre + (size_t)(s * 2 + 0) * 8192); };
    auto wl = [&](int s) { return (const uint2*)(wpre + (size_t)(s * 2 + 1) * 8192); };

    // instantiations: <K, EPI, AFMT, WH, WF, STATS>
    cudaFuncSetAttribute(k_gemm<64, 0, 1, 0, 1, 1>,  cudaFuncAttributeMaxDynamicSharedMemorySize, smb(64));
    cudaFuncSetAttribute(k_gemm<128, 1, 0, 1, 1, 0>, cudaFuncAttributeMaxDynamicSharedMemorySize, smb(128));
    cudaFuncSetAttribute(k_gemm<128, 3, 1, 1, 0, 0>, cudaFuncAttributeMaxDynamicSharedMemorySize, smb(128));
    cudaFuncSetAttribute(k_gemm<128, 2, 0, 0, 1, 1>, cudaFuncAttributeMaxDynamicSharedMemorySize, smb(128));
    cudaFuncSetAttribute(k_gemm<128, 2, 0, 0, 1, 0>, cudaFuncAttributeMaxDynamicSharedMemorySize, smb(128));
    cudaFuncSetAttribute(k_gemm<128, 0, 0, 0, 1, 1>, cudaFuncAttributeMaxDynamicSharedMemorySize, smb(128));
    cudaFuncSetAttribute(k_gemm<128, 0, 0, 0, 1, 0>, cudaFuncAttributeMaxDynamicSharedMemorySize, smb(128));

    const int NB  = (Nn + 255) / 256;
    const int EB  = (Ee + 255) / 256;
    const int EWB = (Nn * 32 + 255) / 256;
    const int CVB = (Nn * 16 + 255) / 256;

    k_zero_counts<<<NB, 256>>>();                                        // 0
    k_prepw<<<9, 256>>>(W_in, Wf, Wa, W_o1, W_o2);                       // 1
    k_cvt<<<CVB, 256>>>(x);                                              // 2
    k_gemm<64, 0, 1, 0, 1, 1><<<GB1, 256, smb(64)>>>(
        nullptr, XH, wh(0), wl(0), b_in, nullptr, T, nullptr);           // 3 <- profiled
    k_detect<<<1, 32>>>((const int*)ei);                                 // 4
    k_hist<<<EB, 256>>>(ei);                                             // 5
    k_dinv<<<NB, 256>>>();                                               // 6
    k_scan<<<1, 1024>>>();                                               // 7
    k_fill<<<EB, 256>>>(ei);                                             // 8
    k_stats2<<<1, 128>>>(gin, btin, GB1);                                // 9
    k_bn<0><<<EWB, 256>>>(T, nullptr, PREV);                             // 10

    for (int l = 0; l < 3; l++) {
        // y0 = sigmoid(PREV @ Wf): fp32 Y0 + fp16 YH (SpMM gather)
        k_gemm<128, 1, 0, 1, 1, 0><<<GB1, 256, smb(128)>>>(
            PREV, nullptr, wh(1 + l), wl(1 + l), nullptr, nullptr, Y0, YH);
        k_spmm<1><<<EWB, 256>>>(nullptr, TH);    // TH = A_hat @ y0 (fp16)
        // y = y0^2 * (TH @ Wa): fp16-A fast path, fp16 -> YH only
        k_gemm<128, 3, 1, 1, 0, 0><<<GB1, 256, smb(128)>>>(
            nullptr, TH, wh(4 + l), wl(4 + l), nullptr, Y0, nullptr, YH);
        k_spmm<0><<<EWB, 256>>>(T, nullptr);     // T = A_hat @ y (fp32)
        if (l < 2) {
            // h = y0 * (T @ Wa): fp32 H + fused BN stats
            k_gemm<128, 2, 0, 0, 1, 1><<<GB1, 256, smb(128)>>>(
                T, nullptr, wh(4 + l), wl(4 + l), nullptr, Y0, H, nullptr);
            k_stats2<<<1, 128>>>(gnorm + l * 128, btnorm + l * 128, GB1);
            k_bn<1><<<EWB, 256>>>(H, PREV, PREV);
        } else {
            k_gemm<128, 2, 0, 0, 1, 0><<<GB1, 256, smb(128)>>>(
                T, nullptr, wh(4 + l), wl(4 + l), nullptr, Y0, H, nullptr);
        }
    }

    // output encoder: Linear -> BN -> ReLU -> Linear (fp32 path)
    k_gemm<128, 0, 0, 0, 1, 1><<<GB1, 256, smb(128)>>>(
        H, nullptr, wh(7), wl(7), b_o1, nullptr, T, nullptr);
    k_stats2<<<1, 128>>>(g_o, bt_o, GB1);
    k_bn<0><<<EWB, 256>>>(T, nullptr, Y0);
    k_gemm<128, 0, 0, 0, 1, 0><<<GB1, 256, smb(128)>>>(
        Y0, nullptr, wh(8), wl(8), b_o2, nullptr, out, nullptr);
}